// round 17
// baseline (speedup 1.0000x reference)
#include <cuda_runtime.h>
#include <cuda_bf16.h>
#include <cstdint>
#include <math.h>

// Problem constants
#define Hn    81
#define G3    243          // 3*H
#define RPAD  244
#define Fn    128
#define Tn    1024
#define Bn    512
#define BPC   4
#define NCTA  128          // 512/4

// =====================================================================
// Device scratch: XG[t][ctab][b(4)][r(244)] floats = 512 MB
// =====================================================================
__device__ float4 g_xg[Tn * NCTA * RPAD];
__device__ float g_h8[Bn * 8];

// ---------- fast activations ----------
static __device__ __forceinline__ float sigm(float x) {
    x = fminf(fmaxf(x, -30.f), 30.f);
    return __fdividef(1.f, 1.f + __expf(-x));
}
static __device__ __forceinline__ float tanh_f(float x) {
    x = fminf(fmaxf(x, -20.f), 20.f);
    float e = __expf(-2.f * x);
    return __fdividef(1.f - e, 1.f + e);
}

// ---------- common mma helpers ----------
static __device__ __forceinline__ uint32_t smem_u32(const void* p) {
    uint32_t a;
    asm("{ .reg .u64 t; cvta.to.shared.u64 t, %1; cvt.u32.u64 %0, t; }"
        : "=r"(a) : "l"(p));
    return a;
}
static __device__ __forceinline__ uint32_t bfpack(float a, float b) {
    uint32_t r;
    asm("cvt.rn.bf16x2.f32 %0, %1, %2;" : "=r"(r) : "f"(b), "f"(a));
    return r;
}
static __device__ __forceinline__ void cvt8(char* thi, char* tlo, int off, float4 v) {
    uint32_t h0 = bfpack(v.x, v.y);
    uint32_t h1 = bfpack(v.z, v.w);
    float fx = __uint_as_float(h0 << 16);
    float fy = __uint_as_float(h0 & 0xffff0000u);
    float fz = __uint_as_float(h1 << 16);
    float fw = __uint_as_float(h1 & 0xffff0000u);
    uint32_t l0 = bfpack(v.x - fx, v.y - fy);
    uint32_t l1 = bfpack(v.z - fz, v.w - fw);
    *(uint2*)(thi + off) = make_uint2(h0, h1);
    *(uint2*)(tlo + off) = make_uint2(l0, l1);
}
static __device__ __forceinline__ void ldx4(uint32_t* r, uint32_t addr) {
    asm volatile("ldmatrix.sync.aligned.m8n8.x4.shared.b16 {%0,%1,%2,%3}, [%4];"
                 : "=r"(r[0]), "=r"(r[1]), "=r"(r[2]), "=r"(r[3]) : "r"(addr));
}
static __device__ __forceinline__ void ldx2(uint32_t* r, uint32_t addr) {
    asm volatile("ldmatrix.sync.aligned.m8n8.x2.shared.b16 {%0,%1}, [%2];"
                 : "=r"(r[0]), "=r"(r[1]) : "r"(addr));
}
static __device__ __forceinline__ void mma16816(float* c, const uint32_t* a,
                                                const uint32_t* b) {
    asm volatile(
        "mma.sync.aligned.m16n8k16.row.col.f32.bf16.bf16.f32 "
        "{%0,%1,%2,%3}, {%4,%5,%6,%7}, {%8,%9}, {%0,%1,%2,%3};"
        : "+f"(c[0]), "+f"(c[1]), "+f"(c[2]), "+f"(c[3])
        : "r"(a[0]), "r"(a[1]), "r"(a[2]), "r"(a[3]), "r"(b[0]), "r"(b[1]));
}

// =====================================================================
// Kernel 1 (R13 winner, verbatim): XG = x @ W_ih^T + b_ih.
// =====================================================================
#define KPITCH   144
#define TILE_SZ  (128 * KPITCH)
#define SM_AHI   0
#define SM_ALO   (SM_AHI + TILE_SZ)
#define SM_BHI   (SM_ALO + TILE_SZ)
#define SM_BLO   (SM_BHI + TILE_SZ)
#define SM_BS    (4 * TILE_SZ)
#define SM_MMA_BYTES (SM_BS + 512)
#define CPITCH   132

__global__ void __launch_bounds__(256, 2) xg_mma(
    const float* __restrict__ x,
    const float* __restrict__ W_ih,
    const float* __restrict__ b_ih)
{
    extern __shared__ char sm[];
    const uint32_t smb = smem_u32(sm);
    float* bsm = (float*)(sm + SM_BS);

    const int tid  = threadIdx.x;
    const int lane = tid & 31;
    const int w    = tid >> 5;
    const int ctab = blockIdx.x;
    const int b0   = ctab * BPC;
    const int t0   = blockIdx.y * 32;
    const int mt   = blockIdx.z;
    const long sbt = (long)Tn * Fn;

    const int wm = (w & 3) * 32;
    const int wn = (w >> 2) * 64;

    int aoff[2], boff[2][2];
    {
        int lr = lane & 15, lk8 = (lane >> 4) * 8;
        aoff[0] = (wm + lr) * KPITCH + lk8 * 2;
        aoff[1] = (wm + 16 + lr) * KPITCH + lk8 * 2;
        int sel = lane >> 3;
        int kk = (sel & 1) * 8;
        #pragma unroll
        for (int nh = 0; nh < 2; nh++) {
            int nrow = wn + nh * 32 + (lane & 7) + (sel >> 1) * 8;
            boff[nh][0] = nrow * KPITCH + kk * 2;
            boff[nh][1] = (nrow + 16) * KPITCH + kk * 2;
        }
    }
    const int r2 = tid >> 1, kh = tid & 1;
    const int bcol = r2 & 3, tcol = r2 >> 2;

    float c[2][8][4];
    #pragma unroll
    for (int mb = 0; mb < 2; mb++)
        #pragma unroll
        for (int nb = 0; nb < 8; nb++)
            #pragma unroll
            for (int q = 0; q < 4; q++) c[mb][nb][q] = 0.f;

    #pragma unroll 1
    for (int kc = 0; kc < 2; kc++) {
        {
            int rg = mt * 128 + r2;
            bool va = (rg < G3);
            const float4* srcA = (const float4*)(W_ih + (long)rg * Fn
                                                 + kc * 64 + kh * 32);
            const float4* srcB = (const float4*)(x + (long)(b0 + bcol) * sbt
                                                 + (long)(t0 + tcol) * Fn
                                                 + kc * 64 + kh * 32);
            #pragma unroll
            for (int i = 0; i < 8; i++) {
                int off = r2 * KPITCH + (kh * 32 + 4 * i) * 2;
                float4 va4 = va ? srcA[i] : make_float4(0.f, 0.f, 0.f, 0.f);
                cvt8(sm + SM_AHI, sm + SM_ALO, off, va4);
                cvt8(sm + SM_BHI, sm + SM_BLO, off, srcB[i]);
            }
        }
        __syncthreads();

        #pragma unroll 1
        for (int ks = 0; ks < 4; ks++) {
            const int kb = ks * 32;
            uint32_t ahi[2][4], alo[2][4];
            ldx4(ahi[0], smb + SM_AHI + aoff[0] + kb);
            ldx4(ahi[1], smb + SM_AHI + aoff[1] + kb);
            ldx4(alo[0], smb + SM_ALO + aoff[0] + kb);
            ldx4(alo[1], smb + SM_ALO + aoff[1] + kb);
            #pragma unroll
            for (int nh = 0; nh < 2; nh++) {
                uint32_t bh[4][2], bl[4][2];
                #pragma unroll
                for (int g = 0; g < 2; g++) {
                    uint32_t r4[4];
                    ldx4(r4, smb + SM_BHI + boff[nh][g] + kb);
                    bh[2*g][0] = r4[0]; bh[2*g][1] = r4[1];
                    bh[2*g+1][0] = r4[2]; bh[2*g+1][1] = r4[3];
                    ldx4(r4, smb + SM_BLO + boff[nh][g] + kb);
                    bl[2*g][0] = r4[0]; bl[2*g][1] = r4[1];
                    bl[2*g+1][0] = r4[2]; bl[2*g+1][1] = r4[3];
                }
                #pragma unroll
                for (int mb = 0; mb < 2; mb++)
                    #pragma unroll
                    for (int j = 0; j < 4; j++) {
                        float* cc = c[mb][nh * 4 + j];
                        mma16816(cc, ahi[mb], bh[j]);
                        mma16816(cc, alo[mb], bh[j]);
                        mma16816(cc, ahi[mb], bl[j]);
                    }
            }
        }
        __syncthreads();
    }

    float* Cs = (float*)sm;
    {
        int lr = lane >> 2;
        int lc = (lane & 3) * 2;
        #pragma unroll
        for (int mb = 0; mb < 2; mb++) {
            int row = wm + 16 * mb + lr;
            #pragma unroll
            for (int nb = 0; nb < 8; nb++) {
                int col = wn + 8 * nb + lc;
                Cs[col * CPITCH + row]           = c[mb][nb][0];
                Cs[(col + 1) * CPITCH + row]     = c[mb][nb][1];
                Cs[col * CPITCH + row + 8]       = c[mb][nb][2];
                Cs[(col + 1) * CPITCH + row + 8] = c[mb][nb][3];
            }
        }
        if (tid < 128) {
            int rg = mt * 128 + tid;
            bsm[tid] = (rg < G3) ? b_ih[rg] : 0.f;
        }
    }
    __syncthreads();
    {
        float* gxf = (float*)g_xg;
        int n  = tid >> 1;
        int rh = tid & 1;
        int tl = n >> 2, b = n & 3;
        long gbase = ((long)(t0 + tl) * NCTA + ctab) * 976 + b * 244 + mt * 128;
        int i0 = rh * 16;
        int i1 = rh ? ((mt == 0) ? 32 : 29) : 16;
        for (int i = i0; i < i1; i++) {
            float4 cv = *(float4*)(Cs + n * CPITCH + 4 * i);
            float4 bv = *(float4*)(bsm + 4 * i);
            cv.x += bv.x; cv.y += bv.y; cv.z += bv.z; cv.w += bv.w;
            *(float4*)(gxf + gbase + 4 * i) = cv;
        }
    }
}

// =====================================================================
// Kernel 2 (v5): TC recurrence with IN-WARP GATES, 1 barrier/step.
// 128 CTAs x 544 threads (17 warps). Warp w owns hidden units
// r in [5w, 5w+5): its M-tile rows are [g0,g1,g2 of each r] (permuted
// W_hh). Gates gathered from C fragments via shfl; h kept in registers;
// h bf16 hi/lo double-buffered in smem for the B operand.
// =====================================================================
#define KP 208
#define HBSZ (8 * KP)      // one [b][k] plane

__global__ void __launch_bounds__(544, 1) gru_tc2(
    const float* __restrict__ W_hh,
    const float* __restrict__ b_hh,
    const float* __restrict__ fc_w,
    const float* __restrict__ fc_b)
{
    __shared__ __align__(16) float4 xgs[2 * RPAD];       // 7808 B
    __shared__ __align__(16) char hb[2][2][HBSZ];        // [buf][hi/lo][b][k]
    __shared__ __align__(16) char scr[2][16 * KP];       // A staging scratch
    __shared__ __align__(16) float hsS[Hn * 4];

    const int tid  = threadIdx.x;
    const int lane = tid & 31;
    const int w    = tid >> 5;         // 0..16
    const int ctab = blockIdx.x;

    // zero both h buffers (incl. pads) and load xg(t=0)
    for (int i = tid; i < 4 * HBSZ / 4; i += 544)
        ((uint32_t*)hb)[i] = 0u;
    if (tid < RPAD) xgs[tid] = g_xg[(long)ctab * RPAD + tid];

    // ---- stage permuted W_hh A-fragments into registers (once) ----
    uint32_t ahi[6][4], alo[6][4];
    {
        const int aoff = (lane & 15) * KP + ((lane >> 4) * 8) * 2;
        const uint32_t scrh_u = smem_u32(scr[0]);
        const uint32_t scrl_u = smem_u32(scr[1]);
        const int srow = tid & 15;          // staging row
        const int kb3  = (tid >> 4) * 3;    // 0..99

        for (int tw = 0; tw < NCTA/NCTA + 16; tw++) {   // 17 tiles
            __syncthreads();
            // stage tile tw: row m -> W_hh row (g*81 + r), r = 5*tw + m/3
            {
                int g  = srow % 3;
                int rl = srow / 3;          // 0..5 (srow 15 -> rl 5 pad)
                int r  = 5 * tw + rl;
                bool vrow = (srow < 15) && (r < Hn);
                #pragma unroll
                for (int j = 0; j < 3; j++) {
                    int k = kb3 + j;
                    if (k < 96) {
                        float v = (vrow && k < Hn) ? W_hh[(g * Hn + r) * Hn + k] : 0.f;
                        __nv_bfloat16 hbv = __float2bfloat16(v);
                        *(__nv_bfloat16*)(scr[0] + srow * KP + k * 2) = hbv;
                        *(__nv_bfloat16*)(scr[1] + srow * KP + k * 2) =
                            __float2bfloat16(v - __bfloat162float(hbv));
                    }
                }
            }
            __syncthreads();
            if (w == tw) {
                #pragma unroll
                for (int kt = 0; kt < 6; kt++) {
                    ldx4(ahi[kt], scrh_u + aoff + kt * 32);
                    ldx4(alo[kt], scrl_u + aoff + kt * 32);
                }
            }
        }
    }

    // per-thread gate item: (r = 5w + rl, batch b)
    const int rl = (lane >> 2) < 5 ? (lane >> 2) : 4;   // clamp for idle lanes
    const int b  = lane & 3;
    const int rg = 5 * w + (lane >> 2);
    const bool valid = (lane < 20) && (rg < Hn);
    float bh3[3] = {0.f, 0.f, 0.f};
    if (valid) {
        bh3[0] = b_hh[0 * Hn + rg];
        bh3[1] = b_hh[1 * Hn + rg];
        bh3[2] = b_hh[2 * Hn + rg];
    }
    float hprev = 0.f;

    float4 q1 = make_float4(0.f, 0.f, 0.f, 0.f);
    if (tid < RPAD) q1 = g_xg[((long)1 * NCTA + ctab) * RPAD + tid];
    __syncthreads();

    const uint32_t hb_u[2][2] = {
        { smem_u32(hb[0][0]), smem_u32(hb[0][1]) },
        { smem_u32(hb[1][0]), smem_u32(hb[1][1]) } };
    const int bofs = (lane & 7) * KP + (((lane >> 3) & 1) * 8) * 2;

    for (int t = 0; t < Tn; t++) {
        const int cur = t & 1, nxt = cur ^ 1;

        float4 q2 = make_float4(0.f, 0.f, 0.f, 0.f);
        if (t + 2 < Tn && tid < RPAD)
            q2 = g_xg[((long)(t + 2) * NCTA + ctab) * RPAD + tid];

        // ---- mma: 3-term split reading hb[cur] ----
        float cA[4] = {0.f, 0.f, 0.f, 0.f};
        float cB[4] = {0.f, 0.f, 0.f, 0.f};
        float cC[4] = {0.f, 0.f, 0.f, 0.f};
        #pragma unroll
        for (int kt = 0; kt < 6; kt++) {
            uint32_t bhf[2], blf[2];
            ldx2(bhf, hb_u[cur][0] + bofs + kt * 32);
            ldx2(blf, hb_u[cur][1] + bofs + kt * 32);
            mma16816(cA, ahi[kt], bhf);
            mma16816(cB, alo[kt], bhf);
            mma16816(cC, ahi[kt], blf);
        }
        float v0 = cA[0] + cB[0] + cC[0];
        float v1 = cA[1] + cB[1] + cC[1];
        float v2 = cA[2] + cB[2] + cC[2];
        float v3 = cA[3] + cB[3] + cC[3];

        // ---- in-warp gather of the 3 gate values for (rl, b) ----
        float hg[3];
        #pragma unroll
        for (int g = 0; g < 3; g++) {
            int m   = 3 * rl + g;                     // 0..14
            int src = ((m & 7) << 2) + (b >> 1);
            float t0 = __shfl_sync(0xffffffffu, v0, src);
            float t1 = __shfl_sync(0xffffffffu, v1, src);
            float t2 = __shfl_sync(0xffffffffu, v2, src);
            float t3 = __shfl_sync(0xffffffffu, v3, src);
            int which = (b & 1) | ((m >> 3) << 1);
            hg[g] = (which == 0) ? t0 : (which == 1) ? t1
                  : (which == 2) ? t2 : t3;
        }

        // ---- gate math (in registers) + h bf16 write to hb[nxt] ----
        if (valid) {
            const float* xgc = (const float*)(xgs + cur * RPAD) + b * 244;
            float xr = xgc[rg];
            float xz = xgc[Hn + rg];
            float xn = xgc[2 * Hn + rg];
            float rr = sigm(xr + hg[0] + bh3[0]);
            float z  = sigm(xz + hg[1] + bh3[1]);
            float n  = tanh_f(xn + rr * (hg[2] + bh3[2]));
            hprev = (1.f - z) * n + z * hprev;
            __nv_bfloat16 hbv = __float2bfloat16(hprev);
            *(__nv_bfloat16*)(hb[nxt][0] + b * KP + rg * 2) = hbv;
            *(__nv_bfloat16*)(hb[nxt][1] + b * KP + rg * 2) =
                __float2bfloat16(hprev - __bfloat162float(hbv));
        }
        if (t + 1 < Tn && tid < RPAD) xgs[nxt * RPAD + tid] = q1;
        q1 = q2;
        __syncthreads();
    }

    // ---- head stage 1 ----
    if (valid) hsS[rg * 4 + b] = hprev;
    __syncthreads();
    if (tid < 32) {
        int bb = tid >> 3, f = tid & 7;
        float a = fc_b[f];
        #pragma unroll 27
        for (int j = 0; j < Hn; j++) a += hsS[j * 4 + bb] * fc_w[f * Hn + j];
        a = a * sigm(a);
        g_h8[(ctab * BPC + bb) * 8 + f] = a;
    }
}

// =====================================================================
// Kernel 3: BN(8) -> fc1 -> silu -> BN(4) -> fc2. One CTA, 512 threads.
// =====================================================================
__global__ void __launch_bounds__(Bn) head_kernel(
    const float* __restrict__ g1, const float* __restrict__ beta1,
    const float* __restrict__ fc1_w, const float* __restrict__ fc1_b,
    const float* __restrict__ g2, const float* __restrict__ beta2,
    const float* __restrict__ fc2_w, const float* __restrict__ fc2_b,
    float* __restrict__ out)
{
    __shared__ float s8[Bn * 8];
    __shared__ float s4[Bn * 4];
    __shared__ float mu1[8], iv1[8], mu2[4], iv2[4];
    const int tid = threadIdx.x;

    for (int i = tid; i < Bn * 8; i += Bn) s8[i] = g_h8[i];
    __syncthreads();

    if (tid < 8) {
        float s = 0.f, ss = 0.f;
        for (int b = 0; b < Bn; b++) { float v = s8[b * 8 + tid]; s += v; ss += v * v; }
        float m = s * (1.f / Bn);
        float var = ss * (1.f / Bn) - m * m;
        mu1[tid] = m;
        iv1[tid] = rsqrtf(var + 1e-5f);
    }
    __syncthreads();

    {
        int b = tid;
        float y[8];
        #pragma unroll
        for (int f = 0; f < 8; f++)
            y[f] = (s8[b * 8 + f] - mu1[f]) * iv1[f] * g1[f] + beta1[f];
        #pragma unroll
        for (int o = 0; o < 4; o++) {
            float a = fc1_b[o];
            #pragma unroll
            for (int f = 0; f < 8; f++) a += y[f] * fc1_w[o * 8 + f];
            a = a * sigm(a);
            s4[b * 4 + o] = a;
        }
    }
    __syncthreads();

    if (tid < 4) {
        float s = 0.f, ss = 0.f;
        for (int b = 0; b < Bn; b++) { float v = s4[b * 4 + tid]; s += v; ss += v * v; }
        float m = s * (1.f / Bn);
        float var = ss * (1.f / Bn) - m * m;
        mu2[tid] = m;
        iv2[tid] = rsqrtf(var + 1e-5f);
    }
    __syncthreads();

    {
        int b = tid;
        float a = fc2_b[0];
        #pragma unroll
        for (int o = 0; o < 4; o++)
            a += ((s4[b * 4 + o] - mu2[o]) * iv2[o] * g2[o] + beta2[o]) * fc2_w[o];
        out[b] = a;
    }
}

// =====================================================================
extern "C" void kernel_launch(void* const* d_in, const int* in_sizes, int n_in,
                              void* d_out, int out_size) {
    const float* x     = (const float*)d_in[0];
    const float* W_ih  = (const float*)d_in[1];
    const float* W_hh  = (const float*)d_in[2];
    const float* b_ih  = (const float*)d_in[3];
    const float* b_hh  = (const float*)d_in[4];
    const float* fc_w  = (const float*)d_in[5];
    const float* fc_b  = (const float*)d_in[6];
    const float* g1    = (const float*)d_in[7];
    const float* beta1 = (const float*)d_in[8];
    const float* fc1_w = (const float*)d_in[9];
    const float* fc1_b = (const float*)d_in[10];
    const float* g2    = (const float*)d_in[11];
    const float* beta2 = (const float*)d_in[12];
    const float* fc2_w = (const float*)d_in[13];
    const float* fc2_b = (const float*)d_in[14];
    float* out = (float*)d_out;

    cudaFuncSetAttribute(xg_mma, cudaFuncAttributeMaxDynamicSharedMemorySize, SM_MMA_BYTES);

    xg_mma<<<dim3(NCTA, 32, 2), 256, SM_MMA_BYTES>>>(x, W_ih, b_ih);
    gru_tc2<<<NCTA, 544>>>(W_hh, b_hh, fc_w, fc_b);
    head_kernel<<<1, Bn>>>(g1, beta1, fc1_w, fc1_b, g2, beta2, fc2_w, fc2_b, out);
}